// round 7
// baseline (speedup 1.0000x reference)
#include <cuda_runtime.h>
#include <cuda_bf16.h>
#include <mma.h>
#include <cmath>

using namespace nvcuda;
typedef __nv_bfloat16 bf16;

// ---------------- problem constants ----------------
#define NWIN   8192
#define TTOK   401408
#define HWI    224
#define HWSQ   50176
#define DIMC   192

__device__ __forceinline__ float tf32r(float v) {
    float r;
    asm("cvt.rna.tf32.f32 %0, %1;" : "=f"(r) : "f"(v));
    return r;
}

// scratch (allocation-free static device arrays)
__device__ float g_qkv [(size_t)TTOK * 576];    // QKV output (scaled/biased/tf32)
__device__ float g_h1  [(size_t)TTOK * DIMC];   // x + attn branch (fp32)
__device__ bf16  g_h1n [(size_t)TTOK * DIMC];   // LN2(h1) in bf16 (MLP input)
__device__ float g_qkvw_t[192 * 576];           // tf32-rounded
__device__ float g_projw_t[192 * 192];          // tf32-rounded
__device__ bf16  g_fc1w_b [192 * 768];          // bf16
__device__ bf16  g_fc2w_b [768 * 192];          // bf16
__device__ float g_bias   [6 * 49 * 49];        // rpb[relidx[r,j]*6+h]

// tf32 fragments (attention path)
typedef wmma::fragment<wmma::matrix_a,16,16,8,wmma::precision::tf32,wmma::row_major> FragA;
typedef wmma::fragment<wmma::matrix_b,16,16,8,wmma::precision::tf32,wmma::row_major> FragB;
typedef wmma::fragment<wmma::matrix_b,16,16,8,wmma::precision::tf32,wmma::col_major> FragBT;
typedef wmma::fragment<wmma::accumulator,16,16,8,float> FragC;
// bf16 fragments (MLP path)
typedef wmma::fragment<wmma::matrix_a,16,16,16,bf16,wmma::row_major> FragAb;
typedef wmma::fragment<wmma::matrix_b,16,16,16,bf16,wmma::row_major> FragBb;
typedef wmma::fragment<wmma::accumulator,16,16,16,float> FragCb;

// ---------------- prelude ----------------
#define W_QKV 110592
#define W_PRJ  36864
#define W_FC1 147456
#define W_FC2 147456
#define N_BIAS 14406
#define PRE_TOT (W_QKV + W_PRJ + W_FC1 + W_FC2 + N_BIAS)

__global__ void prelude(const float* __restrict__ qkvw, const float* __restrict__ projw,
                        const float* __restrict__ fc1w, const float* __restrict__ fc2w,
                        const float* __restrict__ rpb,  const int* __restrict__ relidx)
{
    int i = blockIdx.x * blockDim.x + threadIdx.x;
    if (i < W_QKV) { g_qkvw_t[i] = tf32r(qkvw[i]); return; }
    i -= W_QKV;
    if (i < W_PRJ) { g_projw_t[i] = tf32r(projw[i]); return; }
    i -= W_PRJ;
    if (i < W_FC1) { g_fc1w_b[i] = __float2bfloat16(fc1w[i]); return; }
    i -= W_FC1;
    if (i < W_FC2) { g_fc2w_b[i] = __float2bfloat16(fc2w[i]); return; }
    i -= W_FC2;
    if (i < N_BIAS) {
        int h = i / 2401, rj = i - h * 2401;
        g_bias[i] = rpb[relidx[rj] * 6 + h];
    }
}

// ============================================================================
// Kernel A: batched QKV GEMM over 128-token tiles (3136 CTAs, 256 thr).
//   gather x -> LN1(tf32) in smem -> [128,192]x[192,576] tf32 GEMM
//   (N in 6 chunks of 96, warp tile 2rt x 3ct) -> epilogue (bias, q-scale,
//   tf32 round) -> g_qkv.
// smem: xn f32[128][196] @0 (100352B); st f32[128][100] @100352 (51200B)
// ============================================================================
#define XN_LD 196
#define ST_LD 100
#define QKV_SMEM 151552

__global__ void __launch_bounds__(256, 1)
qkv_gemm(const float* __restrict__ x,
         const float* __restrict__ ln1w, const float* __restrict__ ln1b,
         const float* __restrict__ qkvb)
{
    extern __shared__ float sm[];
    float* xn = sm;
    float* st = sm + 128 * XN_LD;

    const int tid  = threadIdx.x;
    const int wid  = tid >> 5;
    const int lane = tid & 31;
    const int t0   = blockIdx.x * 128;

    // gather: thread owns fixed row r, strides over c by 2
    {
        const int r = tid & 127;
        const int t = t0 + r;
        const int win = t / 49, pos = t - win * 49;
        const int b = win >> 10, wh = (win >> 5) & 31, ww = win & 31;
        const int pi = pos / 7;
        const float* src = x + (size_t)b * DIMC * HWSQ + (wh * 7 + pi) * HWI + (ww * 7 + pos - pi * 7);
        for (int c = tid >> 7; c < DIMC; c += 2)
            xn[r * XN_LD + c] = src[(size_t)c * HWSQ];
    }
    __syncthreads();

    // LN1 -> tf32 (identical math/order to prior rounds)
    for (int r = wid; r < 128; r += 8) {
        float v[6]; float s = 0.f;
#pragma unroll
        for (int q = 0; q < 6; q++) { v[q] = xn[r * XN_LD + lane + q * 32]; s += v[q]; }
#pragma unroll
        for (int o = 16; o; o >>= 1) s += __shfl_xor_sync(~0u, s, o);
        float mu = s * (1.f / 192.f);
        float vs = 0.f;
#pragma unroll
        for (int q = 0; q < 6; q++) { float d = v[q] - mu; vs += d * d; }
#pragma unroll
        for (int o = 16; o; o >>= 1) vs += __shfl_xor_sync(~0u, vs, o);
        float rs = rsqrtf(vs * (1.f / 192.f) + 1e-5f);
#pragma unroll
        for (int q = 0; q < 6; q++) {
            int c = lane + q * 32;
            xn[r * XN_LD + c] = tf32r((v[q] - mu) * rs * ln1w[c] + ln1b[c]);
        }
    }
    __syncthreads();

    const int rtg = wid & 3;     // row-tile group: rows rtg*32 .. +31 (2 tiles)
    const int ctg = wid >> 2;    // 0/1: ct tiles ctg*3 .. +2 within chunk
    const float scale = 0.17677669529663687f;

    for (int chunk = 0; chunk < 6; chunk++) {
        FragC acc[2][3];
#pragma unroll
        for (int i = 0; i < 2; i++)
#pragma unroll
            for (int j = 0; j < 3; j++) wmma::fill_fragment(acc[i][j], 0.f);

        for (int k = 0; k < 24; k++) {
            FragA af[2];
#pragma unroll
            for (int i = 0; i < 2; i++)
                wmma::load_matrix_sync(af[i], xn + (rtg * 32 + i * 16) * XN_LD + k * 8, XN_LD);
#pragma unroll
            for (int j = 0; j < 3; j++) {
                FragB bf;
                wmma::load_matrix_sync(bf, g_qkvw_t + (size_t)k * 8 * 576 + chunk * 96 + (ctg * 3 + j) * 16, 576);
#pragma unroll
                for (int i = 0; i < 2; i++)
                    wmma::mma_sync(acc[i][j], af[i], bf, acc[i][j]);
            }
        }
#pragma unroll
        for (int i = 0; i < 2; i++)
#pragma unroll
            for (int j = 0; j < 3; j++)
                wmma::store_matrix_sync(st + (rtg * 32 + i * 16) * ST_LD + (ctg * 3 + j) * 16,
                                        acc[i][j], ST_LD, wmma::mem_row_major);
        __syncthreads();

        // epilogue: bias, q-scale, tf32 round -> g_qkv (coalesced)
        for (int idx = tid; idx < 128 * 96; idx += 256) {
            int r = idx / 96, cl = idx - r * 96;
            int gc = chunk * 96 + cl;
            float v = st[r * ST_LD + cl] + qkvb[gc];
            if (gc < 192) v *= scale;
            g_qkv[(size_t)(t0 + r) * 576 + gc] = tf32r(v);
        }
        __syncthreads();
    }
}

// ============================================================================
// Kernel B: per-window attention core (512 threads): load qkv slab ->
//   6-head scores/softmax/PV -> tf32 round -> proj -> residual -> LN2.
// smem floats: qkv[64][580]@0  xs[64][196]@37120  sc[64][68]@49664
// ============================================================================
#define QK_LD 580
#define XS_LD 196
#define SC_LD 68
#define ATTN_SMEM 216064

__global__ void __launch_bounds__(512, 1)
attn_core(const float* __restrict__ x,
          const float* __restrict__ projb,
          const float* __restrict__ ln2w, const float* __restrict__ ln2b)
{
    extern __shared__ float sm[];
    float* qkv = sm;
    float* xs  = sm + 37120;
    float* sc  = sm + 49664;

    const int tid  = threadIdx.x;
    const int wid  = tid >> 5;
    const int lane = tid & 31;

    const int win = blockIdx.x;
    const int b   = win >> 10;
    const int wh  = (win >> 5) & 31;
    const int ww  = win & 31;
    const float* xb = x + (size_t)b * DIMC * HWSQ;

    // load qkv rows 0..48 (float4 coalesced: 580/4=145, 49*580/4=7105)
    {
        const float4* src = (const float4*)(g_qkv + (size_t)win * 49 * 576);
        float4* dst = (float4*)qkv;
        for (int idx = tid; idx < 49 * 144; idx += 512) {
            int r = idx / 144, c4 = idx - r * 144;
            dst[r * 145 + c4] = src[idx];
        }
        // zero pad rows 49..63
        float4 z = make_float4(0.f, 0.f, 0.f, 0.f);
        for (int idx = 7105 + tid; idx < 9280; idx += 512) dst[idx] = z;
    }
    __syncthreads();

    // ---- attention: one head per iteration (round-4 loop) ----
    for (int h = 0; h < 6; h++) {
        {   // scores: 16 tiles, one per warp
            int rt = wid >> 2, ct = wid & 3;
            FragC acc; wmma::fill_fragment(acc, 0.f);
#pragma unroll
            for (int k = 0; k < 4; k++) {
                FragA af; wmma::load_matrix_sync(af, qkv + rt * 16 * QK_LD + h * 32 + k * 8, QK_LD);
                FragBT bf; wmma::load_matrix_sync(bf, qkv + ct * 16 * QK_LD + 192 + h * 32 + k * 8, QK_LD);
                wmma::mma_sync(acc, af, bf, acc);
            }
            wmma::store_matrix_sync(sc + rt * 16 * SC_LD + ct * 16, acc, SC_LD, wmma::mem_row_major);
        }
        __syncthreads();

        const float* bh = g_bias + h * 2401;
        for (int r = wid; r < 49; r += 16) {
            float* srow = sc + r * SC_LD;
            int j0 = lane, j1 = lane + 32;
            float v0 = srow[j0] + bh[r * 49 + j0];
            float v1 = (j1 < 49) ? srow[j1] + bh[r * 49 + j1] : -1e30f;
            float m = fmaxf(v0, v1);
#pragma unroll
            for (int o = 16; o; o >>= 1) m = fmaxf(m, __shfl_xor_sync(~0u, m, o));
            float e0 = expf(v0 - m);
            float e1 = (j1 < 49) ? expf(v1 - m) : 0.f;
            float s = e0 + e1;
#pragma unroll
            for (int o = 16; o; o >>= 1) s += __shfl_xor_sync(~0u, s, o);
            float inv = 1.f / s;
            srow[j0] = tf32r(e0 * inv);
            if (j1 < 49) srow[j1] = tf32r(e1 * inv);
        }
        __syncthreads();

        if (wid < 8) { // PV: 8 tiles
            int rt = wid >> 1, ct = wid & 1;
            FragC acc; wmma::fill_fragment(acc, 0.f);
#pragma unroll
            for (int k = 0; k < 8; k++) {
                FragA af; wmma::load_matrix_sync(af, sc + rt * 16 * SC_LD + k * 8, SC_LD);
                FragB bf; wmma::load_matrix_sync(bf, qkv + (size_t)k * 8 * QK_LD + 384 + h * 32 + ct * 16, QK_LD);
                wmma::mma_sync(acc, af, bf, acc);
            }
            wmma::store_matrix_sync(xs + rt * 16 * XS_LD + h * 32 + ct * 16, acc, XS_LD, wmma::mem_row_major);
        }
        __syncthreads();
    }

    // tf32-round attn output (proj A operand); pad rows are zero already
    for (int idx = tid; idx < 49 * 192; idx += 512) {
        int r = idx / 192, c = idx - r * 192;
        xs[r * XS_LD + c] = tf32r(xs[r * XS_LD + c]);
    }
    __syncthreads();

    // ---- proj GEMM: k-outer, 3 accumulators (round-4 structure) ----
    {
        const int rt = wid & 3, ctb = wid >> 2;
        FragC acc[3];
#pragma unroll
        for (int j = 0; j < 3; j++) wmma::fill_fragment(acc[j], 0.f);
        for (int k = 0; k < 24; k++) {
            FragA af; wmma::load_matrix_sync(af, xs + rt * 16 * XS_LD + k * 8, XS_LD);
#pragma unroll
            for (int j = 0; j < 3; j++) {
                FragB bf;
                wmma::load_matrix_sync(bf, g_projw_t + (size_t)k * 8 * 192 + (ctb + 4 * j) * 16, 192);
                wmma::mma_sync(acc[j], af, bf, acc[j]);
            }
        }
#pragma unroll
        for (int j = 0; j < 3; j++)
            wmma::store_matrix_sync(qkv + rt * 16 * XS_LD + (ctb + 4 * j) * 16, acc[j], XS_LD, wmma::mem_row_major);
    }
    __syncthreads();

    // residual: qkv(ld XS_LD) += x + projb
    for (int idx = tid; idx < DIMC * 49; idx += 512) {
        int c = idx / 49, r = idx - c * 49;
        int i = r / 7, j = r - i * 7;
        float xv = xb[(size_t)c * HWSQ + (wh * 7 + i) * HWI + (ww * 7 + j)];
        qkv[r * XS_LD + c] += xv + projb[c];
    }
    __syncthreads();

    // LN2 + write h1 (fp32) / h1n (bf16)
    size_t base = (size_t)win * 49 * DIMC;
    for (int r = wid; r < 49; r += 16) {
        float v[6]; float s = 0.f;
#pragma unroll
        for (int q = 0; q < 6; q++) { v[q] = qkv[r * XS_LD + lane + q * 32]; s += v[q]; }
#pragma unroll
        for (int o = 16; o; o >>= 1) s += __shfl_xor_sync(~0u, s, o);
        float mu = s * (1.f / 192.f);
        float vs = 0.f;
#pragma unroll
        for (int q = 0; q < 6; q++) { float d = v[q] - mu; vs += d * d; }
#pragma unroll
        for (int o = 16; o; o >>= 1) vs += __shfl_xor_sync(~0u, vs, o);
        float rs = rsqrtf(vs * (1.f / 192.f) + 1e-5f);
#pragma unroll
        for (int q = 0; q < 6; q++) {
            int c = lane + q * 32;
            g_h1 [base + r * DIMC + c] = v[q];
            g_h1n[base + r * DIMC + c] = __float2bfloat16((v[q] - mu) * rs * ln2w[c] + ln2b[c]);
        }
    }
}

// ============================================================================
// Kernel C: round-4 MLP, unchanged (256 threads, 2 CTAs/SM, bf16).
// ============================================================================
#define AS_LD 200
#define MD_LD 196
#define MLP_SMEM 101376

__global__ void __launch_bounds__(256, 2)
mlp_kernel(const float* __restrict__ fc1b, const float* __restrict__ fc2b,
           float* __restrict__ out)
{
    extern __shared__ char smc[];
    bf16*  as   = (bf16*)smc;
    float* mid  = (float*)(smc + 25600);
    bf16*  midb = (bf16*)(smc + 75776);

    const int tid = threadIdx.x;
    const int wid = tid >> 5;
    const int t0  = blockIdx.x * 64;
    const int rt  = wid & 3;
    const int ctb = wid >> 2;   // 0 or 1

    {
        const uint4* src = (const uint4*)g_h1n;
        uint4* dst = (uint4*)as;
        for (int idx = tid; idx < 64 * 24; idx += 256) {
            int r = idx / 24, c = idx - r * 24;
            dst[r * 25 + c] = src[(size_t)(t0 + r) * 24 + c];
        }
    }
    __syncthreads();

    FragCb acc2[6];
#pragma unroll
    for (int j = 0; j < 6; j++) wmma::fill_fragment(acc2[j], 0.f);

    for (int chunk = 0; chunk < 4; chunk++) {
#pragma unroll
        for (int g = 0; g < 2; g++) {
            FragCb acc[3];
#pragma unroll
            for (int j = 0; j < 3; j++) wmma::fill_fragment(acc[j], 0.f);
            for (int k = 0; k < 12; k++) {
                FragAb af; wmma::load_matrix_sync(af, as + rt * 16 * AS_LD + k * 16, AS_LD);
#pragma unroll
                for (int j = 0; j < 3; j++) {
                    int ct = ctb + 2 * (3 * g + j);
                    FragBb bf;
                    wmma::load_matrix_sync(bf, g_fc1w_b + (size_t)k * 16 * 768 + chunk * 192 + ct * 16, 768);
                    wmma::mma_sync(acc[j], af, bf, acc[j]);
                }
            }
#pragma unroll
            for (int j = 0; j < 3; j++) {
                int ct = ctb + 2 * (3 * g + j);
                wmma::store_matrix_sync(mid + rt * 16 * MD_LD + ct * 16, acc[j], MD_LD, wmma::mem_row_major);
            }
        }
        __syncthreads();

        for (int idx = tid; idx < 64 * 192; idx += 256) {
            int r = idx / 192, c = idx - r * 192;
            float v = mid[r * MD_LD + c] + fc1b[chunk * 192 + c];
            midb[r * AS_LD + c] = __float2bfloat16(0.5f * v * (1.f + erff(v * 0.70710678118654752f)));
        }
        __syncthreads();

        for (int kk = 0; kk < 12; kk++) {
            FragAb af; wmma::load_matrix_sync(af, midb + rt * 16 * AS_LD + kk * 16, AS_LD);
#pragma unroll
            for (int j = 0; j < 6; j++) {
                int ct = ctb + 2 * j;
                FragBb bf;
                wmma::load_matrix_sync(bf, g_fc2w_b + (size_t)(chunk * 192 + kk * 16) * 192 + ct * 16, 192);
                wmma::mma_sync(acc2[j], af, bf, acc2[j]);
            }
        }
        __syncthreads();
    }

#pragma unroll
    for (int j = 0; j < 6; j++) {
        int ct = ctb + 2 * j;
        wmma::store_matrix_sync(mid + rt * 16 * MD_LD + ct * 16, acc2[j], MD_LD, wmma::mem_row_major);
    }
    __syncthreads();

    for (int idx = tid; idx < 64 * 192; idx += 256) {
        int r = idx & 63;
        int c = idx >> 6;
        int t = t0 + r;
        int win = t / 49; int pos = t - win * 49;
        int b  = win >> 10;
        int wh = (win >> 5) & 31;
        int ww = win & 31;
        int pi = pos / 7;
        int hh = wh * 7 + pi;
        int wx = ww * 7 + (pos - pi * 7);
        out[((size_t)(b * DIMC + c)) * HWSQ + hh * HWI + wx] =
            mid[r * MD_LD + c] + g_h1[(size_t)t * 192 + c] + fc2b[c];
    }
}

// ============================================================================
extern "C" void kernel_launch(void* const* d_in, const int* in_sizes, int n_in,
                              void* d_out, int out_size)
{
    (void)in_sizes; (void)n_in; (void)out_size;
    const float* x     = (const float*)d_in[0];
    const float* ln1w  = (const float*)d_in[1];
    const float* ln1b  = (const float*)d_in[2];
    const float* qkvw  = (const float*)d_in[3];
    const float* qkvb  = (const float*)d_in[4];
    const float* projw = (const float*)d_in[5];
    const float* projb = (const float*)d_in[6];
    const float* rpb   = (const float*)d_in[7];
    const float* ln2w  = (const float*)d_in[8];
    const float* ln2b  = (const float*)d_in[9];
    const float* fc1w  = (const float*)d_in[10];
    const float* fc1b  = (const float*)d_in[11];
    const float* fc2w  = (const float*)d_in[12];
    const float* fc2b  = (const float*)d_in[13];
    const int*   ridx  = (const int*)  d_in[14];
    float* out = (float*)d_out;

    cudaFuncSetAttribute(qkv_gemm,  cudaFuncAttributeMaxDynamicSharedMemorySize, QKV_SMEM);
    cudaFuncSetAttribute(attn_core, cudaFuncAttributeMaxDynamicSharedMemorySize, ATTN_SMEM);
    cudaFuncSetAttribute(mlp_kernel, cudaFuncAttributeMaxDynamicSharedMemorySize, MLP_SMEM);

    prelude<<<(PRE_TOT + 511) / 512, 512>>>(qkvw, projw, fc1w, fc2w, rpb, ridx);

    qkv_gemm<<<TTOK / 128, 256, QKV_SMEM>>>(x, ln1w, ln1b, qkvb);

    attn_core<<<NWIN, 512, ATTN_SMEM>>>(x, projb, ln2w, ln2b);

    mlp_kernel<<<TTOK / 64, 256, MLP_SMEM>>>(fc1b, fc2b, out);
}

// round 9
// speedup vs baseline: 1.0702x; 1.0702x over previous
#include <cuda_runtime.h>
#include <cuda_bf16.h>
#include <mma.h>
#include <cmath>
#include <cstdint>

using namespace nvcuda;
typedef __nv_bfloat16 bf16;

// ---------------- problem constants ----------------
#define NWIN   8192
#define TTOK   401408
#define HWI    224
#define HWSQ   50176
#define DIMC   192

__device__ __forceinline__ float tf32r(float v) {
    float r;
    asm("cvt.rna.tf32.f32 %0, %1;" : "=f"(r) : "f"(v));
    return r;
}

// scratch (allocation-free static device arrays)
__device__ float g_qkv [(size_t)TTOK * 576];    // QKV (scaled/biased/tf32)
__device__ float g_attn[(size_t)TTOK * DIMC];   // attention out (raw fp32)
__device__ float g_h1  [(size_t)TTOK * DIMC];   // x + attn branch (fp32)
__device__ bf16  g_h1n [(size_t)TTOK * DIMC];   // LN2(h1) bf16
__device__ float g_qkvw_t[192 * 576];
__device__ float g_projw_t[192 * 192];
__device__ bf16  g_fc1w_b [192 * 768];
__device__ bf16  g_fc2w_b [768 * 192];
__device__ float g_bias   [6 * 49 * 49];

typedef wmma::fragment<wmma::matrix_a,16,16,8,wmma::precision::tf32,wmma::row_major> FragA;
typedef wmma::fragment<wmma::matrix_b,16,16,8,wmma::precision::tf32,wmma::row_major> FragB;
typedef wmma::fragment<wmma::matrix_b,16,16,8,wmma::precision::tf32,wmma::col_major> FragBT;
typedef wmma::fragment<wmma::accumulator,16,16,8,float> FragC;
typedef wmma::fragment<wmma::matrix_a,16,16,16,bf16,wmma::row_major> FragAb;
typedef wmma::fragment<wmma::matrix_b,16,16,16,bf16,wmma::row_major> FragBb;
typedef wmma::fragment<wmma::accumulator,16,16,16,float> FragCb;

// ---------------- prelude (round-4 weights) ----------------
#define W_QKV 110592
#define W_PRJ  36864
#define W_FC1 147456
#define W_FC2 147456
#define N_BIAS 14406
#define PRE_TOT (W_QKV + W_PRJ + W_FC1 + W_FC2 + N_BIAS)

__global__ void prelude(const float* __restrict__ qkvw, const float* __restrict__ projw,
                        const float* __restrict__ fc1w, const float* __restrict__ fc2w,
                        const float* __restrict__ rpb,  const int* __restrict__ relidx)
{
    int i = blockIdx.x * blockDim.x + threadIdx.x;
    if (i < W_QKV) { g_qkvw_t[i] = tf32r(qkvw[i]); return; }
    i -= W_QKV;
    if (i < W_PRJ) { g_projw_t[i] = tf32r(projw[i]); return; }
    i -= W_PRJ;
    if (i < W_FC1) { g_fc1w_b[i] = __float2bfloat16(fc1w[i]); return; }
    i -= W_FC1;
    if (i < W_FC2) { g_fc2w_b[i] = __float2bfloat16(fc2w[i]); return; }
    i -= W_FC2;
    if (i < N_BIAS) {
        int h = i / 2401, rj = i - h * 2401;
        g_bias[i] = rpb[relidx[rj] * 6 + h];
    }
}

// ============================================================================
// Kernel A: batched QKV GEMM (unchanged from round 7)
// ============================================================================
#define XN_LD 196
#define ST_LD 100
#define QKV_SMEM 151552

__global__ void __launch_bounds__(256, 1)
qkv_gemm(const float* __restrict__ x,
         const float* __restrict__ ln1w, const float* __restrict__ ln1b,
         const float* __restrict__ qkvb)
{
    extern __shared__ float sm[];
    float* xn = sm;
    float* st = sm + 128 * XN_LD;

    const int tid  = threadIdx.x;
    const int wid  = tid >> 5;
    const int lane = tid & 31;
    const int t0   = blockIdx.x * 128;

    {
        const int r = tid & 127;
        const int t = t0 + r;
        const int win = t / 49, pos = t - win * 49;
        const int b = win >> 10, wh = (win >> 5) & 31, ww = win & 31;
        const int pi = pos / 7;
        const float* src = x + (size_t)b * DIMC * HWSQ + (wh * 7 + pi) * HWI + (ww * 7 + pos - pi * 7);
        for (int c = tid >> 7; c < DIMC; c += 2)
            xn[r * XN_LD + c] = src[(size_t)c * HWSQ];
    }
    __syncthreads();

    for (int r = wid; r < 128; r += 8) {
        float v[6]; float s = 0.f;
#pragma unroll
        for (int q = 0; q < 6; q++) { v[q] = xn[r * XN_LD + lane + q * 32]; s += v[q]; }
#pragma unroll
        for (int o = 16; o; o >>= 1) s += __shfl_xor_sync(~0u, s, o);
        float mu = s * (1.f / 192.f);
        float vs = 0.f;
#pragma unroll
        for (int q = 0; q < 6; q++) { float d = v[q] - mu; vs += d * d; }
#pragma unroll
        for (int o = 16; o; o >>= 1) vs += __shfl_xor_sync(~0u, vs, o);
        float rs = rsqrtf(vs * (1.f / 192.f) + 1e-5f);
#pragma unroll
        for (int q = 0; q < 6; q++) {
            int c = lane + q * 32;
            xn[r * XN_LD + c] = tf32r((v[q] - mu) * rs * ln1w[c] + ln1b[c]);
        }
    }
    __syncthreads();

    const int rtg = wid & 3;
    const int ctg = wid >> 2;
    const float scale = 0.17677669529663687f;

    for (int chunk = 0; chunk < 6; chunk++) {
        FragC acc[2][3];
#pragma unroll
        for (int i = 0; i < 2; i++)
#pragma unroll
            for (int j = 0; j < 3; j++) wmma::fill_fragment(acc[i][j], 0.f);

        for (int k = 0; k < 24; k++) {
            FragA af[2];
#pragma unroll
            for (int i = 0; i < 2; i++)
                wmma::load_matrix_sync(af[i], xn + (rtg * 32 + i * 16) * XN_LD + k * 8, XN_LD);
#pragma unroll
            for (int j = 0; j < 3; j++) {
                FragB bf;
                wmma::load_matrix_sync(bf, g_qkvw_t + (size_t)k * 8 * 576 + chunk * 96 + (ctg * 3 + j) * 16, 576);
#pragma unroll
                for (int i = 0; i < 2; i++)
                    wmma::mma_sync(acc[i][j], af[i], bf, acc[i][j]);
            }
        }
#pragma unroll
        for (int i = 0; i < 2; i++)
#pragma unroll
            for (int j = 0; j < 3; j++)
                wmma::store_matrix_sync(st + (rtg * 32 + i * 16) * ST_LD + (ctg * 3 + j) * 16,
                                        acc[i][j], ST_LD, wmma::mem_row_major);
        __syncthreads();

        for (int idx = tid; idx < 128 * 96; idx += 256) {
            int r = idx / 96, cl = idx - r * 96;
            int gc = chunk * 96 + cl;
            float v = st[r * ST_LD + cl] + qkvb[gc];
            if (gc < 192) v *= scale;
            g_qkv[(size_t)(t0 + r) * 576 + gc] = tf32r(v);
        }
        __syncthreads();
    }
}

// ============================================================================
// Kernel B: per window-head attention (grid (NWIN,6), 128 threads, ~45KB smem
// -> ~5 CTAs/SM). qs/ks/vs [64][36] f32, sc [64][68] f32.
// Numerics identical to round 4 (same ops, order, rounding points).
// ============================================================================
#define H_LD 36
#define SC_LD 68
#define AH_SMEM ((3 * 64 * H_LD + 64 * SC_LD) * 4)   // 45056

__global__ void __launch_bounds__(128, 5)
attn_heads()
{
    extern __shared__ float sm[];
    float* qs = sm;
    float* ks = sm + 64 * H_LD;
    float* vs = sm + 2 * 64 * H_LD;
    float* sc = sm + 3 * 64 * H_LD;

    const int tid  = threadIdx.x;
    const int wid  = tid >> 5;      // 0..3
    const int lane = tid & 31;
    const int win  = blockIdx.x;
    const int h    = blockIdx.y;

    // load Q/K/V head slices (rows 0..48), float4 coalesced; zero pad rows
    {
        const float* base = g_qkv + (size_t)win * 49 * 576 + h * 32;
        for (int idx = tid; idx < 3 * 49 * 8; idx += 128) {
            int m = idx / 392, rem = idx - m * 392;
            int r = rem >> 3, c4 = rem & 7;
            float4 v = *(const float4*)(base + (size_t)r * 576 + m * 192 + c4 * 4);
            float* dst = (m == 0 ? qs : (m == 1 ? ks : vs));
            *(float4*)(dst + r * H_LD + c4 * 4) = v;
        }
        float4 z = make_float4(0.f, 0.f, 0.f, 0.f);
        for (int idx = tid; idx < 3 * 15 * 8; idx += 128) {
            int m = idx / 120, rem = idx - m * 120;
            int r = 49 + (rem >> 3), c4 = rem & 7;
            float* dst = (m == 0 ? qs : (m == 1 ? ks : vs));
            *(float4*)(dst + r * H_LD + c4 * 4) = z;
        }
    }
    __syncthreads();

    // scores: warp w owns rt=w; A fragments held, B streamed (20 loads/16 mma)
    {
        FragA af[4];
#pragma unroll
        for (int k = 0; k < 4; k++)
            wmma::load_matrix_sync(af[k], qs + wid * 16 * H_LD + k * 8, H_LD);
#pragma unroll
        for (int ct = 0; ct < 4; ct++) {
            FragC acc; wmma::fill_fragment(acc, 0.f);
#pragma unroll
            for (int k = 0; k < 4; k++) {
                FragBT bf; wmma::load_matrix_sync(bf, ks + ct * 16 * H_LD + k * 8, H_LD);
                wmma::mma_sync(acc, af[k], bf, acc);
            }
            wmma::store_matrix_sync(sc + wid * 16 * SC_LD + ct * 16, acc, SC_LD, wmma::mem_row_major);
        }
    }
    __syncthreads();

    // softmax (+ bias), identical to round 4
    {
        const float* bh = g_bias + h * 2401;
        for (int r = wid; r < 49; r += 4) {
            float* srow = sc + r * SC_LD;
            int j0 = lane, j1 = lane + 32;
            float v0 = srow[j0] + bh[r * 49 + j0];
            float v1 = (j1 < 49) ? srow[j1] + bh[r * 49 + j1] : -1e30f;
            float m = fmaxf(v0, v1);
#pragma unroll
            for (int o = 16; o; o >>= 1) m = fmaxf(m, __shfl_xor_sync(~0u, m, o));
            float e0 = expf(v0 - m);
            float e1 = (j1 < 49) ? expf(v1 - m) : 0.f;
            float s = e0 + e1;
#pragma unroll
            for (int o = 16; o; o >>= 1) s += __shfl_xor_sync(~0u, s, o);
            float inv = 1.f / s;
            srow[j0] = tf32r(e0 * inv);
            if (j1 < 49) srow[j1] = tf32r(e1 * inv);
        }
    }
    __syncthreads();

    // PV: warp w owns rt=w; P fragments held in regs (24 loads/16 mma)
    {
        FragA pf[8];
#pragma unroll
        for (int k = 0; k < 8; k++)
            wmma::load_matrix_sync(pf[k], sc + wid * 16 * SC_LD + k * 8, SC_LD);
#pragma unroll
        for (int ct = 0; ct < 2; ct++) {
            FragC acc; wmma::fill_fragment(acc, 0.f);
#pragma unroll
            for (int k = 0; k < 8; k++) {
                FragB bf; wmma::load_matrix_sync(bf, vs + k * 8 * H_LD + ct * 16, H_LD);
                wmma::mma_sync(acc, pf[k], bf, acc);
            }
            wmma::store_matrix_sync(qs + wid * 16 * H_LD + ct * 16, acc, H_LD, wmma::mem_row_major);
        }
    }
    __syncthreads();

    // write attn-out rows 0..48 (raw fp32) to g_attn head slice
    {
        float* base = g_attn + (size_t)win * 49 * DIMC + h * 32;
        for (int idx = tid; idx < 49 * 8; idx += 128) {
            int r = idx >> 3, c4 = idx & 7;
            *(float4*)(base + (size_t)r * DIMC + c4 * 4) = *(float4*)(qs + r * H_LD + c4 * 4);
        }
    }
}

// ============================================================================
// Kernel C: proj + residual + LN2 over 128-token tiles (3136 CTAs, 256 thr).
// smem: xs f32[128][196] @0 ; st f32[128][196] @ 128*196
// ============================================================================
#define PJ_LD 196
#define PROJ_SMEM (2 * 128 * PJ_LD * 4)   // 200704

__global__ void __launch_bounds__(256, 1)
proj_ln2(const float* __restrict__ x,
         const float* __restrict__ projb,
         const float* __restrict__ ln2w, const float* __restrict__ ln2b)
{
    extern __shared__ float sm[];
    float* xs = sm;
    float* st = sm + 128 * PJ_LD;

    const int tid  = threadIdx.x;
    const int wid  = tid >> 5;
    const int lane = tid & 31;
    const int t0   = blockIdx.x * 128;

    // load attn-out, tf32-round (same rounding point as round 4)
    for (int idx = tid; idx < 128 * 192; idx += 256) {
        int r = idx / 192, c = idx - r * 192;
        xs[r * PJ_LD + c] = tf32r(g_attn[(size_t)(t0 + r) * 192 + c]);
    }
    __syncthreads();

    // proj GEMM: 2 chunks of 96 cols, warp tile 2rt x 3ct
    const int rtg = wid & 3;
    const int ctg = wid >> 2;
    for (int chunk = 0; chunk < 2; chunk++) {
        FragC acc[2][3];
#pragma unroll
        for (int i = 0; i < 2; i++)
#pragma unroll
            for (int j = 0; j < 3; j++) wmma::fill_fragment(acc[i][j], 0.f);

        for (int k = 0; k < 24; k++) {
            FragA af[2];
#pragma unroll
            for (int i = 0; i < 2; i++)
                wmma::load_matrix_sync(af[i], xs + (rtg * 32 + i * 16) * PJ_LD + k * 8, PJ_LD);
#pragma unroll
            for (int j = 0; j < 3; j++) {
                FragB bf;
                wmma::load_matrix_sync(bf, g_projw_t + (size_t)k * 8 * 192 + chunk * 96 + (ctg * 3 + j) * 16, 192);
#pragma unroll
                for (int i = 0; i < 2; i++)
                    wmma::mma_sync(acc[i][j], af[i], bf, acc[i][j]);
            }
        }
#pragma unroll
        for (int i = 0; i < 2; i++)
#pragma unroll
            for (int j = 0; j < 3; j++)
                wmma::store_matrix_sync(st + (rtg * 32 + i * 16) * PJ_LD + chunk * 96 + (ctg * 3 + j) * 16,
                                        acc[i][j], PJ_LD, wmma::mem_row_major);
    }
    __syncthreads();

    // residual: st += x + projb (gather x like qkv_gemm)
    {
        const int r = tid & 127;
        const int t = t0 + r;
        const int win = t / 49, pos = t - win * 49;
        const int b = win >> 10, wh = (win >> 5) & 31, ww = win & 31;
        const int pi = pos / 7;
        const float* src = x + (size_t)b * DIMC * HWSQ + (wh * 7 + pi) * HWI + (ww * 7 + pos - pi * 7);
        for (int c = tid >> 7; c < DIMC; c += 2)
            st[r * PJ_LD + c] += src[(size_t)c * HWSQ] + projb[c];
    }
    __syncthreads();

    // LN2 + write h1 (fp32) / h1n (bf16)
    for (int r = wid; r < 128; r += 8) {
        float v[6]; float s = 0.f;
#pragma unroll
        for (int q = 0; q < 6; q++) { v[q] = st[r * PJ_LD + lane + q * 32]; s += v[q]; }
#pragma unroll
        for (int o = 16; o; o >>= 1) s += __shfl_xor_sync(~0u, s, o);
        float mu = s * (1.f / 192.f);
        float vs = 0.f;
#pragma unroll
        for (int q = 0; q < 6; q++) { float d = v[q] - mu; vs += d * d; }
#pragma unroll
        for (int o = 16; o; o >>= 1) vs += __shfl_xor_sync(~0u, vs, o);
        float rs = rsqrtf(vs * (1.f / 192.f) + 1e-5f);
        size_t base = (size_t)(t0 + r) * DIMC;
#pragma unroll
        for (int q = 0; q < 6; q++) {
            int c = lane + q * 32;
            g_h1 [base + c] = v[q];
            g_h1n[base + c] = __float2bfloat16((v[q] - mu) * rs * ln2w[c] + ln2b[c]);
        }
    }
}

// ============================================================================
// Kernel D: round-4 MLP (256 threads, 2 CTAs/SM, bf16) — known good.
// ============================================================================
#define AS_LD 200
#define MD_LD 196
#define MLP_SMEM 101376

__global__ void __launch_bounds__(256, 2)
mlp_kernel(const float* __restrict__ fc1b, const float* __restrict__ fc2b,
           float* __restrict__ out)
{
    extern __shared__ char smc[];
    bf16*  as   = (bf16*)smc;
    float* mid  = (float*)(smc + 25600);
    bf16*  midb = (bf16*)(smc + 75776);

    const int tid = threadIdx.x;
    const int wid = tid >> 5;
    const int t0  = blockIdx.x * 64;
    const int rt  = wid & 3;
    const int ctb = wid >> 2;

    {
        const uint4* src = (const uint4*)g_h1n;
        uint4* dst = (uint4*)as;
        for (int idx = tid; idx < 64 * 24; idx += 256) {
            int r = idx / 24, c = idx - r * 24;
            dst[r * 25 + c] = src[(size_t)(t0 + r) * 24 + c];
        }
    }
    __syncthreads();

    FragCb acc2[6];
#pragma unroll
    for (int j = 0; j < 6; j++) wmma::fill_fragment(acc2[j], 0.f);

    for (int chunk = 0; chunk < 4; chunk++) {
#pragma unroll
        for (int g = 0; g < 2; g++) {
            FragCb acc[3];
#pragma unroll
            for (int j = 0; j < 3; j++) wmma::fill_fragment(acc[j], 0.f);
            for (int k = 0; k < 12; k++) {
                FragAb af; wmma::load_matrix_sync(af, as + rt * 16 * AS_LD + k * 16, AS_LD);
#pragma unroll
                for (int j = 0; j < 3; j++) {
                    int ct = ctb + 2 * (3 * g + j);
                    FragBb bf;
                    wmma::load_matrix_sync(bf, g_fc1w_b + (size_t)k * 16 * 768 + chunk * 192 + ct * 16, 768);
                    wmma::mma_sync(acc[j], af, bf, acc[j]);
                }
            }
#pragma unroll
            for (int j = 0; j < 3; j++) {
                int ct = ctb + 2 * (3 * g + j);
                wmma::store_matrix_sync(mid + rt * 16 * MD_LD + ct * 16, acc[j], MD_LD, wmma::mem_row_major);
            }
        }
        __syncthreads();

        for (int idx = tid; idx < 64 * 192; idx += 256) {
            int r = idx / 192, c = idx - r * 192;
            float v = mid[r * MD_LD + c] + fc1b[chunk * 192 + c];
            midb[r * AS_LD + c] = __float2bfloat16(0.5f * v * (1.f + erff(v * 0.70710678118654752f)));
        }
        __syncthreads();

        for (int kk = 0; kk < 12; kk++) {
            FragAb af; wmma::load_matrix_sync(af, midb + rt * 16 * AS_LD + kk * 16, AS_LD);
#pragma unroll
            for (int j = 0; j < 6; j++) {
                int ct = ctb + 2 * j;
                FragBb bf;
                wmma::load_matrix_sync(bf, g_fc2w_b + (size_t)(chunk * 192 + kk * 16) * 192 + ct * 16, 192);
                wmma::mma_sync(acc2[j], af, bf, acc2[j]);
            }
        }
        __syncthreads();
    }

#pragma unroll
    for (int j = 0; j < 6; j++) {
        int ct = ctb + 2 * j;
        wmma::store_matrix_sync(mid + rt * 16 * MD_LD + ct * 16, acc2[j], MD_LD, wmma::mem_row_major);
    }
    __syncthreads();

    for (int idx = tid; idx < 64 * 192; idx += 256) {
        int r = idx & 63;
        int c = idx >> 6;
        int t = t0 + r;
        int win = t / 49; int pos = t - win * 49;
        int b  = win >> 10;
        int wh = (win >> 5) & 31;
        int ww = win & 31;
        int pi = pos / 7;
        int hh = wh * 7 + pi;
        int wx = ww * 7 + (pos - pi * 7);
        out[((size_t)(b * DIMC + c)) * HWSQ + hh * HWI + wx] =
            mid[r * MD_LD + c] + g_h1[(size_t)t * 192 + c] + fc2b[c];
    }
}

// ============================================================================
extern "C" void kernel_launch(void* const* d_in, const int* in_sizes, int n_in,
                              void* d_out, int out_size)
{
    (void)in_sizes; (void)n_in; (void)out_size;
    const float* x     = (const float*)d_in[0];
    const float* ln1w  = (const float*)d_in[1];
    const float* ln1b  = (const float*)d_in[2];
    const float* qkvw  = (const float*)d_in[3];
    const float* qkvb  = (const float*)d_in[4];
    const float* projw = (const float*)d_in[5];
    const float* projb = (const float*)d_in[6];
    const float* rpb   = (const float*)d_in[7];
    const float* ln2w  = (const float*)d_in[8];
    const float* ln2b  = (const float*)d_in[9];
    const float* fc1w  = (const float*)d_in[10];
    const float* fc1b  = (const float*)d_in[11];
    const float* fc2w  = (const float*)d_in[12];
    const float* fc2b  = (const float*)d_in[13];
    const int*   ridx  = (const int*)  d_in[14];
    float* out = (float*)d_out;

    cudaFuncSetAttribute(qkv_gemm,   cudaFuncAttributeMaxDynamicSharedMemorySize, QKV_SMEM);
    cudaFuncSetAttribute(attn_heads, cudaFuncAttributeMaxDynamicSharedMemorySize, AH_SMEM);
    cudaFuncSetAttribute(proj_ln2,   cudaFuncAttributeMaxDynamicSharedMemorySize, PROJ_SMEM);
    cudaFuncSetAttribute(mlp_kernel, cudaFuncAttributeMaxDynamicSharedMemorySize, MLP_SMEM);

    prelude<<<(PRE_TOT + 511) / 512, 512>>>(qkvw, projw, fc1w, fc2w, rpb, ridx);

    qkv_gemm<<<TTOK / 128, 256, QKV_SMEM>>>(x, ln1w, ln1b, qkvb);

    dim3 ag(NWIN, 6);
    attn_heads<<<ag, 128, AH_SMEM>>>();

    proj_ln2<<<TTOK / 128, 256, PROJ_SMEM>>>(x, projb, ln2w, ln2b);

    mlp_kernel<<<TTOK / 64, 256, MLP_SMEM>>>(fc1b, fc2b, out);
}

// round 10
// speedup vs baseline: 1.2301x; 1.1494x over previous
#include <cuda_runtime.h>
#include <cuda_bf16.h>
#include <cuda_fp16.h>
#include <mma.h>
#include <cmath>
#include <cstdint>

using namespace nvcuda;
typedef __nv_bfloat16 bf16;

// ---------------- problem constants ----------------
#define NWIN   8192
#define TTOK   401408
#define HWI    224
#define HWSQ   50176
#define DIMC   192

// scratch (allocation-free static device arrays)
__device__ __half g_qkvh [(size_t)TTOK * 576];   // QKV (scaled/biased, fp16)
__device__ __half g_attnh[(size_t)TTOK * DIMC];  // attention out (fp16)
__device__ float  g_h1  [(size_t)TTOK * DIMC];   // x + attn branch (fp32)
__device__ bf16   g_h1n [(size_t)TTOK * DIMC];   // LN2(h1) bf16
__device__ __half g_qkvw_h[192 * 576];
__device__ __half g_projw_h[192 * 192];
__device__ bf16   g_fc1w_b [192 * 768];
__device__ bf16   g_fc2w_b [768 * 192];
__device__ float  g_bias   [6 * 49 * 49];

// fp16 fragments (attention path)
typedef wmma::fragment<wmma::matrix_a,16,16,16,__half,wmma::row_major> FragAh;
typedef wmma::fragment<wmma::matrix_b,16,16,16,__half,wmma::row_major> FragBh;
typedef wmma::fragment<wmma::matrix_b,16,16,16,__half,wmma::col_major> FragBTh;
typedef wmma::fragment<wmma::accumulator,16,16,16,float> FragCf;
// bf16 fragments (MLP path)
typedef wmma::fragment<wmma::matrix_a,16,16,16,bf16,wmma::row_major> FragAb;
typedef wmma::fragment<wmma::matrix_b,16,16,16,bf16,wmma::row_major> FragBb;

// ---------------- prelude ----------------
#define W_QKV 110592
#define W_PRJ  36864
#define W_FC1 147456
#define W_FC2 147456
#define N_BIAS 14406
#define PRE_TOT (W_QKV + W_PRJ + W_FC1 + W_FC2 + N_BIAS)

__global__ void prelude(const float* __restrict__ qkvw, const float* __restrict__ projw,
                        const float* __restrict__ fc1w, const float* __restrict__ fc2w,
                        const float* __restrict__ rpb,  const int* __restrict__ relidx)
{
    int i = blockIdx.x * blockDim.x + threadIdx.x;
    if (i < W_QKV) { g_qkvw_h[i] = __float2half_rn(qkvw[i]); return; }
    i -= W_QKV;
    if (i < W_PRJ) { g_projw_h[i] = __float2half_rn(projw[i]); return; }
    i -= W_PRJ;
    if (i < W_FC1) { g_fc1w_b[i] = __float2bfloat16(fc1w[i]); return; }
    i -= W_FC1;
    if (i < W_FC2) { g_fc2w_b[i] = __float2bfloat16(fc2w[i]); return; }
    i -= W_FC2;
    if (i < N_BIAS) {
        int h = i / 2401, rj = i - h * 2401;
        g_bias[i] = rpb[relidx[rj] * 6 + h];
    }
}

// ============================================================================
// Kernel A: batched QKV GEMM, fp16 (3136 CTAs, 256 thr).
// smem: xnf f32[128][196]@0 (100352, overlaid by st f32[128][100] after LN1);
//       xh half[128][200]@100352 (51200). total 151552
// ============================================================================
#define XN_LD 196
#define XH_LD 200
#define ST_LD 100
#define QKV_SMEM 151552

__global__ void __launch_bounds__(256, 1)
qkv_gemm(const float* __restrict__ x,
         const float* __restrict__ ln1w, const float* __restrict__ ln1b,
         const float* __restrict__ qkvb)
{
    extern __shared__ char smc[];
    float*  xnf = (float*)smc;
    float*  st  = (float*)smc;                 // overlay (used after LN1)
    __half* xh  = (__half*)(smc + 100352);

    const int tid  = threadIdx.x;
    const int wid  = tid >> 5;
    const int lane = tid & 31;
    const int t0   = blockIdx.x * 128;

    // gather x (fp32)
    {
        const int r = tid & 127;
        const int t = t0 + r;
        const int win = t / 49, pos = t - win * 49;
        const int b = win >> 10, wh = (win >> 5) & 31, ww = win & 31;
        const int pi = pos / 7;
        const float* src = x + (size_t)b * DIMC * HWSQ + (wh * 7 + pi) * HWI + (ww * 7 + pos - pi * 7);
        for (int c = tid >> 7; c < DIMC; c += 2)
            xnf[r * XN_LD + c] = src[(size_t)c * HWSQ];
    }
    __syncthreads();

    // LN1 (fp32 stats) -> fp16 A operand
    for (int r = wid; r < 128; r += 8) {
        float v[6]; float s = 0.f;
#pragma unroll
        for (int q = 0; q < 6; q++) { v[q] = xnf[r * XN_LD + lane + q * 32]; s += v[q]; }
#pragma unroll
        for (int o = 16; o; o >>= 1) s += __shfl_xor_sync(~0u, s, o);
        float mu = s * (1.f / 192.f);
        float vs = 0.f;
#pragma unroll
        for (int q = 0; q < 6; q++) { float d = v[q] - mu; vs += d * d; }
#pragma unroll
        for (int o = 16; o; o >>= 1) vs += __shfl_xor_sync(~0u, vs, o);
        float rs = rsqrtf(vs * (1.f / 192.f) + 1e-5f);
#pragma unroll
        for (int q = 0; q < 6; q++) {
            int c = lane + q * 32;
            xh[r * XH_LD + c] = __float2half_rn((v[q] - mu) * rs * ln1w[c] + ln1b[c]);
        }
    }
    __syncthreads();

    const int rtg = wid & 3;
    const int ctg = wid >> 2;
    const float scale = 0.17677669529663687f;

    for (int chunk = 0; chunk < 6; chunk++) {
        FragCf acc[2][3];
#pragma unroll
        for (int i = 0; i < 2; i++)
#pragma unroll
            for (int j = 0; j < 3; j++) wmma::fill_fragment(acc[i][j], 0.f);

        for (int k = 0; k < 12; k++) {
            FragAh af[2];
#pragma unroll
            for (int i = 0; i < 2; i++)
                wmma::load_matrix_sync(af[i], xh + (rtg * 32 + i * 16) * XH_LD + k * 16, XH_LD);
#pragma unroll
            for (int j = 0; j < 3; j++) {
                FragBh bf;
                wmma::load_matrix_sync(bf, g_qkvw_h + (size_t)k * 16 * 576 + chunk * 96 + (ctg * 3 + j) * 16, 576);
#pragma unroll
                for (int i = 0; i < 2; i++)
                    wmma::mma_sync(acc[i][j], af[i], bf, acc[i][j]);
            }
        }
#pragma unroll
        for (int i = 0; i < 2; i++)
#pragma unroll
            for (int j = 0; j < 3; j++)
                wmma::store_matrix_sync(st + (rtg * 32 + i * 16) * ST_LD + (ctg * 3 + j) * 16,
                                        acc[i][j], ST_LD, wmma::mem_row_major);
        __syncthreads();

        // epilogue: bias, q-scale, fp16 round -> g_qkvh
        for (int idx = tid; idx < 128 * 96; idx += 256) {
            int r = idx / 96, cl = idx - r * 96;
            int gc = chunk * 96 + cl;
            float v = st[r * ST_LD + cl] + qkvb[gc];
            if (gc < 192) v *= scale;
            g_qkvh[(size_t)(t0 + r) * 576 + gc] = __float2half_rn(v);
        }
        __syncthreads();
    }
}

// ============================================================================
// Kernel B: per window-head attention, fp16 (grid (NWIN,6), 128 thr, 42KB).
// smem: qs/ks/vs half[64][40] @0/5120/10240; pb half[64][72] @15360;
//       sc f32[64][68] @24576. total 41984 -> ~5 CTAs/SM
// ============================================================================
#define H_LDH 40
#define PB_LD 72
#define SC_LD 68
#define AH_SMEM 41984

__global__ void __launch_bounds__(128, 5)
attn_heads()
{
    extern __shared__ char smc[];
    __half* qs = (__half*)smc;
    __half* ks = (__half*)(smc + 5120);
    __half* vs = (__half*)(smc + 10240);
    __half* pb = (__half*)(smc + 15360);
    float*  sc = (float*)(smc + 24576);

    const int tid  = threadIdx.x;
    const int wid  = tid >> 5;      // 0..3
    const int lane = tid & 31;
    const int win  = blockIdx.x;
    const int h    = blockIdx.y;

    // load Q/K/V head slices (rows 0..48, 32 halves = 4 float4 per row)
    {
        const __half* base = g_qkvh + (size_t)win * 49 * 576 + h * 32;
        for (int idx = tid; idx < 3 * 49 * 4; idx += 128) {
            int m = idx / 196, rem = idx - m * 196;
            int r = rem >> 2, c8 = rem & 3;
            float4 v = *(const float4*)(base + (size_t)r * 576 + m * 192 + c8 * 8);
            __half* dst = (m == 0 ? qs : (m == 1 ? ks : vs));
            *(float4*)(dst + r * H_LDH + c8 * 8) = v;
        }
        // zero pad rows 49..63 of q/k/v and ALL of pb (pad cols must be 0)
        float4 z = make_float4(0.f, 0.f, 0.f, 0.f);
        for (int idx = tid; idx < 3 * 15 * 4; idx += 128) {
            int m = idx / 60, rem = idx - m * 60;
            int r = 49 + (rem >> 2), c8 = rem & 3;
            __half* dst = (m == 0 ? qs : (m == 1 ? ks : vs));
            *(float4*)(dst + r * H_LDH + c8 * 8) = z;
        }
        for (int idx = tid; idx < 576; idx += 128)   // 64*72 halves = 576 f4
            *(float4*)(pb + idx * 8) = z;
    }
    __syncthreads();

    // scores: warp w owns rt=w; A held (2 frags), B streamed
    {
        FragAh af[2];
#pragma unroll
        for (int k = 0; k < 2; k++)
            wmma::load_matrix_sync(af[k], qs + wid * 16 * H_LDH + k * 16, H_LDH);
#pragma unroll
        for (int ct = 0; ct < 4; ct++) {
            FragCf acc; wmma::fill_fragment(acc, 0.f);
#pragma unroll
            for (int k = 0; k < 2; k++) {
                FragBTh bf; wmma::load_matrix_sync(bf, ks + ct * 16 * H_LDH + k * 16, H_LDH);
                wmma::mma_sync(acc, af[k], bf, acc);
            }
            wmma::store_matrix_sync(sc + wid * 16 * SC_LD + ct * 16, acc, SC_LD, wmma::mem_row_major);
        }
    }
    __syncthreads();

    // softmax (+ bias) fp32, probs -> fp16 pb
    {
        const float* bh = g_bias + h * 2401;
        for (int r = wid; r < 49; r += 4) {
            float* srow = sc + r * SC_LD;
            int j0 = lane, j1 = lane + 32;
            float v0 = srow[j0] + bh[r * 49 + j0];
            float v1 = (j1 < 49) ? srow[j1] + bh[r * 49 + j1] : -1e30f;
            float m = fmaxf(v0, v1);
#pragma unroll
            for (int o = 16; o; o >>= 1) m = fmaxf(m, __shfl_xor_sync(~0u, m, o));
            float e0 = expf(v0 - m);
            float e1 = (j1 < 49) ? expf(v1 - m) : 0.f;
            float s = e0 + e1;
#pragma unroll
            for (int o = 16; o; o >>= 1) s += __shfl_xor_sync(~0u, s, o);
            float inv = 1.f / s;
            __half* prow = pb + r * PB_LD;
            prow[j0] = __float2half_rn(e0 * inv);
            if (j1 < 49) prow[j1] = __float2half_rn(e1 * inv);
        }
    }
    __syncthreads();

    // PV: warp w owns rt=w; P held (4 frags); output staged in sc (fp32)
    {
        FragAh pf[4];
#pragma unroll
        for (int k = 0; k < 4; k++)
            wmma::load_matrix_sync(pf[k], pb + wid * 16 * PB_LD + k * 16, PB_LD);
#pragma unroll
        for (int ct = 0; ct < 2; ct++) {
            FragCf acc; wmma::fill_fragment(acc, 0.f);
#pragma unroll
            for (int k = 0; k < 4; k++) {
                FragBh bf; wmma::load_matrix_sync(bf, vs + k * 16 * H_LDH + ct * 16, H_LDH);
                wmma::mma_sync(acc, pf[k], bf, acc);
            }
            wmma::store_matrix_sync(sc + wid * 16 * SC_LD + ct * 16, acc, SC_LD, wmma::mem_row_major);
        }
    }
    __syncthreads();

    // attn-out rows 0..48 -> fp16 g_attnh (2 floats -> half2 per thread)
    {
        __half* base = g_attnh + (size_t)win * 49 * DIMC + h * 32;
        for (int idx = tid; idx < 49 * 16; idx += 128) {
            int r = idx >> 4, c2 = idx & 15;
            __half2 h2 = __floats2half2_rn(sc[r * SC_LD + c2 * 2], sc[r * SC_LD + c2 * 2 + 1]);
            *(__half2*)(base + (size_t)r * DIMC + c2 * 2) = h2;
        }
    }
}

// ============================================================================
// Kernel C: proj (fp16) + residual + LN2 over 128-token tiles (3136 CTAs).
// smem: xh half[128][200]@0 (51200); st f32[128][196]@51200 (100352). 151552
// ============================================================================
#define PJ_LD 196
#define PROJ_SMEM 151552

__global__ void __launch_bounds__(256, 1)
proj_ln2(const float* __restrict__ x,
         const float* __restrict__ projb,
         const float* __restrict__ ln2w, const float* __restrict__ ln2b)
{
    extern __shared__ char smc[];
    __half* xh = (__half*)smc;
    float*  st = (float*)(smc + 51200);

    const int tid  = threadIdx.x;
    const int wid  = tid >> 5;
    const int lane = tid & 31;
    const int t0   = blockIdx.x * 128;

    // load attn-out (already fp16)
    {
        const float4* src = (const float4*)(g_attnh + (size_t)t0 * DIMC);
        for (int idx = tid; idx < 128 * 24; idx += 256) {   // 192 halves = 24 f4
            int r = idx / 24, c8 = idx - r * 24;
            *(float4*)(xh + r * XH_LD + c8 * 8) = src[idx];
        }
    }
    __syncthreads();

    // proj GEMM fp16: 2 chunks of 96 cols, warp tile 2rt x 3ct
    const int rtg = wid & 3;
    const int ctg = wid >> 2;
    for (int chunk = 0; chunk < 2; chunk++) {
        FragCf acc[2][3];
#pragma unroll
        for (int i = 0; i < 2; i++)
#pragma unroll
            for (int j = 0; j < 3; j++) wmma::fill_fragment(acc[i][j], 0.f);

        for (int k = 0; k < 12; k++) {
            FragAh af[2];
#pragma unroll
            for (int i = 0; i < 2; i++)
                wmma::load_matrix_sync(af[i], xh + (rtg * 32 + i * 16) * XH_LD + k * 16, XH_LD);
#pragma unroll
            for (int j = 0; j < 3; j++) {
                FragBh bf;
                wmma::load_matrix_sync(bf, g_projw_h + (size_t)k * 16 * 192 + chunk * 96 + (ctg * 3 + j) * 16, 192);
#pragma unroll
                for (int i = 0; i < 2; i++)
                    wmma::mma_sync(acc[i][j], af[i], bf, acc[i][j]);
            }
        }
#pragma unroll
        for (int i = 0; i < 2; i++)
#pragma unroll
            for (int j = 0; j < 3; j++)
                wmma::store_matrix_sync(st + (rtg * 32 + i * 16) * PJ_LD + chunk * 96 + (ctg * 3 + j) * 16,
                                        acc[i][j], PJ_LD, wmma::mem_row_major);
    }
    __syncthreads();

    // residual: st += x + projb
    {
        const int r = tid & 127;
        const int t = t0 + r;
        const int win = t / 49, pos = t - win * 49;
        const int b = win >> 10, wh = (win >> 5) & 31, ww = win & 31;
        const int pi = pos / 7;
        const float* src = x + (size_t)b * DIMC * HWSQ + (wh * 7 + pi) * HWI + (ww * 7 + pos - pi * 7);
        for (int c = tid >> 7; c < DIMC; c += 2)
            st[r * PJ_LD + c] += src[(size_t)c * HWSQ] + projb[c];
    }
    __syncthreads();

    // LN2 + write h1 (fp32) / h1n (bf16)
    for (int r = wid; r < 128; r += 8) {
        float v[6]; float s = 0.f;
#pragma unroll
        for (int q = 0; q < 6; q++) { v[q] = st[r * PJ_LD + lane + q * 32]; s += v[q]; }
#pragma unroll
        for (int o = 16; o; o >>= 1) s += __shfl_xor_sync(~0u, s, o);
        float mu = s * (1.f / 192.f);
        float vs = 0.f;
#pragma unroll
        for (int q = 0; q < 6; q++) { float d = v[q] - mu; vs += d * d; }
#pragma unroll
        for (int o = 16; o; o >>= 1) vs += __shfl_xor_sync(~0u, vs, o);
        float rs = rsqrtf(vs * (1.f / 192.f) + 1e-5f);
        size_t base = (size_t)(t0 + r) * DIMC;
#pragma unroll
        for (int q = 0; q < 6; q++) {
            int c = lane + q * 32;
            g_h1 [base + c] = v[q];
            g_h1n[base + c] = __float2bfloat16((v[q] - mu) * rs * ln2w[c] + ln2b[c]);
        }
    }
}

// ============================================================================
// Kernel D: round-4 MLP (256 threads, 2 CTAs/SM, bf16) — known good.
// ============================================================================
#define AS_LD 200
#define MD_LD 196
#define MLP_SMEM 101376

__global__ void __launch_bounds__(256, 2)
mlp_kernel(const float* __restrict__ fc1b, const float* __restrict__ fc2b,
           float* __restrict__ out)
{
    extern __shared__ char smc[];
    bf16*  as   = (bf16*)smc;
    float* mid  = (float*)(smc + 25600);
    bf16*  midb = (bf16*)(smc + 75776);

    const int tid = threadIdx.x;
    const int wid = tid >> 5;
    const int t0  = blockIdx.x * 64;
    const int rt  = wid & 3;
    const int ctb = wid >> 2;

    {
        const uint4* src = (const uint4*)g_h1n;
        uint4* dst = (uint4*)as;
        for (int idx = tid; idx < 64 * 24; idx += 256) {
            int r = idx / 24, c = idx - r * 24;
            dst[r * 25 + c] = src[(size_t)(t0 + r) * 24 + c];
        }
    }
    __syncthreads();

    wmma::fragment<wmma::accumulator,16,16,16,float> acc2[6];
#pragma unroll
    for (int j = 0; j < 6; j++) wmma::fill_fragment(acc2[j], 0.f);

    for (int chunk = 0; chunk < 4; chunk++) {
#pragma unroll
        for (int g = 0; g < 2; g++) {
            wmma::fragment<wmma::accumulator,16,16,16,float> acc[3];
#pragma unroll
            for (int j = 0; j < 3; j++) wmma::fill_fragment(acc[j], 0.f);
            for (int k = 0; k < 12; k++) {
                FragAb af; wmma::load_matrix_sync(af, as + rt * 16 * AS_LD + k * 16, AS_LD);
#pragma unroll
                for (int j = 0; j < 3; j++) {
                    int ct = ctb + 2 * (3 * g + j);
                    FragBb bf;
                    wmma::load_matrix_sync(bf, g_fc1w_b + (size_t)k * 16 * 768 + chunk * 192 + ct * 16, 768);
                    wmma::mma_sync(acc[j], af, bf, acc[j]);
                }
            }
#pragma unroll
            for (int j = 0; j < 3; j++) {
                int ct = ctb + 2 * (3 * g + j);
                wmma::store_matrix_sync(mid + rt * 16 * MD_LD + ct * 16, acc[j], MD_LD, wmma::mem_row_major);
            }
        }
        __syncthreads();

        for (int idx = tid; idx < 64 * 192; idx += 256) {
            int r = idx / 192, c = idx - r * 192;
            float v = mid[r * MD_LD + c] + fc1b[chunk * 192 + c];
            midb[r * AS_LD + c] = __float2bfloat16(0.5f * v * (1.f + erff(v * 0.70710678118654752f)));
        }
        __syncthreads();

        for (int kk = 0; kk < 12; kk++) {
            FragAb af; wmma::load_matrix_sync(af, midb + rt * 16 * AS_LD + kk * 16, AS_LD);
#pragma unroll
            for (int j = 0; j < 6; j++) {
                int ct = ctb + 2 * j;
                FragBb bf;
                wmma::load_matrix_sync(bf, g_fc2w_b + (size_t)(chunk * 192 + kk * 16) * 192 + ct * 16, 192);
                wmma::mma_sync(acc2[j], af, bf, acc2[j]);
            }
        }
        __syncthreads();
    }

#pragma unroll
    for (int j = 0; j < 6; j++) {
        int ct = ctb + 2 * j;
        wmma::store_matrix_sync(mid + rt * 16 * MD_LD + ct * 16, acc2[j], MD_LD, wmma::mem_row_major);
    }
    __syncthreads();

    for (int idx = tid; idx < 64 * 192; idx += 256) {
        int r = idx & 63;
        int c = idx >> 6;
        int t = t0 + r;
        int win = t / 49; int pos = t - win * 49;
        int b  = win >> 10;
        int wh = (win >> 5) & 31;
        int ww = win & 31;
        int pi = pos / 7;
        int hh = wh * 7 + pi;
        int wx = ww * 7 + (pos - pi * 7);
        out[((size_t)(b * DIMC + c)) * HWSQ + hh * HWI + wx] =
            mid[r * MD_LD + c] + g_h1[(size_t)t * 192 + c] + fc2b[c];
    }
}

// ============================================================================
extern "C" void kernel_launch(void* const* d_in, const int* in_sizes, int n_in,
                              void* d_out, int out_size)
{
    (void)in_sizes; (void)n_in; (void)out_size;
    const float* x     = (const float*)d_in[0];
    const float* ln1w  = (const float*)d_in[1];
    const float* ln1b  = (const float*)d_in[2];
    const float* qkvw  = (const float*)d_in[3];
    const float* qkvb  = (const float*)d_in[4];
    const float* projw = (const float*)d_in[5];
    const float* projb = (const float*)d_in[6];
    const float* rpb   = (const float*)d_in[7];
    const float* ln2w  = (const float*)d_in[8];
    const float* ln2b  = (const float*)d_in[9];
    const float* fc1w  = (const float*)d_in[10];
    const float* fc1b  = (const float*)d_in[11];
    const float* fc2w  = (const float*)d_in[12];
    const float* fc2b  = (const float*)d_in[13];
    const int*   ridx  = (const int*)  d_in[14];
    float* out = (float*)d_out;

    cudaFuncSetAttribute(qkv_gemm,   cudaFuncAttributeMaxDynamicSharedMemorySize, QKV_SMEM);
    cudaFuncSetAttribute(attn_heads, cudaFuncAttributeMaxDynamicSharedMemorySize, AH_SMEM);
    cudaFuncSetAttribute(proj_ln2,   cudaFuncAttributeMaxDynamicSharedMemorySize, PROJ_SMEM);
    cudaFuncSetAttribute(mlp_kernel, cudaFuncAttributeMaxDynamicSharedMemorySize, MLP_SMEM);

    prelude<<<(PRE_TOT + 511) / 512, 512>>>(qkvw, projw, fc1w, fc2w, rpb, ridx);

    qkv_gemm<<<TTOK / 128, 256, QKV_SMEM>>>(x, ln1w, ln1b, qkvb);

    dim3 ag(NWIN, 6);
    attn_heads<<<ag, 128, AH_SMEM>>>();

    proj_ln2<<<TTOK / 128, 256, PROJ_SMEM>>>(x, projb, ln2w, ln2b);

    mlp_kernel<<<TTOK / 64, 256, MLP_SMEM>>>(fc1b, fc2b, out);
}